// round 3
// baseline (speedup 1.0000x reference)
#include <cuda_runtime.h>
#include <math.h>

#define NN        21
#define NN2       441
#define NFEAT     128
#define FC1_OUT   512
#define FC2_OUT   512
#define FC3_OUT   256
#define FC1_K     441
#define FC2_K     512
#define FC3_K     512

#define NBLK      41           // b0 GCN | b1-16 FC1 | b17-32 FC2 | b33-40 FC3
#define NTHREADS  512

// ---- global scratch (allocation-free) ----
__device__ float g_v[448];
__device__ float g_x1[512];
__device__ float g_x2[512];

// ---- subset grid barriers: generation flag + self-resetting counter ----
// slot stride 32 uints = 128 B to keep each barrier on its own cache line
__device__ unsigned          g_cnt[3 * 32];
__device__ volatile unsigned g_flag[3 * 32];

__device__ __forceinline__ void gbar(int i, unsigned participants) {
    __syncthreads();
    if (threadIdx.x == 0) {
        __threadfence();
        unsigned* cnt = &g_cnt[i * 32];
        volatile unsigned* flag = &g_flag[i * 32];
        unsigned old = *flag;
        if (atomicAdd(cnt, 1u) == participants - 1u) {
            *cnt = 0u;                       // all arrived; safe to reset
            __threadfence();
            atomicAdd((unsigned*)flag, 1u);  // release
        } else {
            while (*flag == old) { }
        }
        __threadfence();
    }
    __syncthreads();
}

// dynamic smem: weights [0,65536) | sx [65536,67584) | red [67584,69632)
#define SMEM_BYTES 69632

__global__ void __launch_bounds__(NTHREADS, 1)
fused_net_kernel(const float* __restrict__ state,
                 const int*   __restrict__ edge_index, int n_edges,
                 const float* __restrict__ W1,  const float* __restrict__ b1,
                 const float* __restrict__ W2,  const float* __restrict__ b2,
                 const float* __restrict__ Wf1, const float* __restrict__ bf1,
                 const float* __restrict__ Wf2, const float* __restrict__ bf2,
                 const float* __restrict__ Wf3, const float* __restrict__ bf3,
                 float* __restrict__ out)
{
    extern __shared__ char smem[];
    const int t = threadIdx.x;
    const int b = blockIdx.x;

    if (b == 0) {
        // ================= GCN front-end (batch element 0 only) ============
        float* sA    = (float*)smem;              // 448
        float* sBufA = sA    + 448;               // 448
        float* sBufB = sBufA + 448;               // 448
        float* sX    = sBufB + 448;               // 21*128
        float* sW1g  = sX    + NN * NFEAT;        // 128*21
        float* sW2g  = sW1g  + NFEAT * NN;        // 448
        float* sb1   = sW2g  + 448;               // 32
        float* sb2   = sb1   + 32;                // 32
        float* sdinv = sb2   + 32;                // 32

        if (t >= 448) {
            // ---- adjacency group: 64 threads, named barrier 1 ----
            const int u = t - 448;
            for (int i = u; i < NN2; i += 64) sA[i] = 0.f;
            asm volatile("bar.sync 1, 64;" ::: "memory");
            for (int e = u; e < n_edges; e += 64) {
                int r = edge_index[e];
                int c = edge_index[n_edges + e];
                atomicAdd(&sA[r * NN + c], 1.0f);
            }
            asm volatile("bar.sync 1, 64;" ::: "memory");
            if (u < NN) sA[u * NN + u] += 1.0f;
            asm volatile("bar.sync 1, 64;" ::: "memory");
            if (u < NN) {
                float d = 0.f;
                #pragma unroll
                for (int i = 0; i < NN; i++) d += sA[i * NN + u];
                sdinv[u] = (d > 0.f) ? rsqrtf(d) : 0.f;
            }
            asm volatile("bar.sync 1, 64;" ::: "memory");
            for (int i = u; i < NN2; i += 64) {
                int ii = i / NN, jj = i % NN;
                sA[i] *= sdinv[ii] * sdinv[jj];
            }
        } else {
            // ---- h1 group: 448 threads, named barrier 2 ----
            const float4* X4  = (const float4*)state;
            const float4* W14 = (const float4*)W1;
            float4* sX4  = (float4*)sX;
            float4* sW14 = (float4*)sW1g;
            for (int i = t; i < (NN * NFEAT) / 4; i += 448) sX4[i]  = X4[i];
            for (int i = t; i < (NFEAT * NN) / 4; i += 448) sW14[i] = W14[i];
            if (t < NN2) sW2g[t] = W2[t];
            if (t < NN)  sb1[t] = b1[t];
            if (t >= 32 && t < 32 + NN) sb2[t - 32] = b2[t - 32];
            asm volatile("bar.sync 2, 448;" ::: "memory");
            if (t < NN2) {                 // h1 = X @ W1
                int i = t / NN, j = t % NN;
                float acc = 0.f;
                #pragma unroll 8
                for (int f = 0; f < NFEAT; f++) acc += sX[i * NFEAT + f] * sW1g[f * NN + j];
                sBufA[t] = acc;
            }
        }
        __syncthreads();

        if (t < NN2) {                     // g1 = A @ h1 + b1
            int i = t / NN, j = t % NN;
            float acc = sb1[j];
            #pragma unroll
            for (int k = 0; k < NN; k++) acc += sA[i * NN + k] * sBufA[k * NN + j];
            sBufB[t] = acc;
        }
        __syncthreads();

        if (t < NN2) {                     // h2 = g1 @ W2
            int i = t / NN, j = t % NN;
            float acc = 0.f;
            #pragma unroll
            for (int f = 0; f < NN; f++) acc += sBufB[i * NN + f] * sW2g[f * NN + j];
            sBufA[t] = acc;
        }
        __syncthreads();

        if (t < NN2) {                     // v = A @ h2 + b2
            int i = t / NN, j = t % NN;
            float acc = sb2[j];
            #pragma unroll
            for (int k = 0; k < NN; k++) acc += sA[i * NN + k] * sBufA[k * NN + j];
            g_v[t] = acc;
        }

        gbar(0, 17);                       // publish v to FC1 blocks
        return;
    }

    // ======================= FC blocks =====================================
    float* ws  = (float*)smem;                    // [K x 32]
    float* sx  = (float*)(smem + 65536);          // [512]
    float* red = (float*)(smem + 67584);          // [512]

    const int j  = t & 31;
    const int kg = t >> 5;                        // 0..15

    if (b <= 16) {
        // ---------------- FC1: full K=441, 32 outputs ----------------------
        const int jt = b - 1;
        {   // preload weights (float4): 441 rows x 8 quads
            const float4* W4 = (const float4*)Wf1;
            float4* ws4 = (float4*)ws;
            for (int i = t; i < FC1_K * 8; i += NTHREADS) {
                int k = i >> 3, c = i & 7;
                ws4[k * 8 + c] = W4[k * (FC1_OUT / 4) + jt * 8 + c];
            }
        }
        gbar(0, 17);                               // wait for v
        if (t < FC1_K) sx[t] = __ldcg(&g_v[t]);
        __syncthreads();
        float acc = 0.f;
        #pragma unroll 4
        for (int k = kg; k < FC1_K; k += 16) acc += sx[k] * ws[k * 32 + j];
        red[t] = acc;
        __syncthreads();
        if (t < 32) {
            float s = red[t];
            #pragma unroll
            for (int g = 1; g < 16; g++) s += red[g * 32 + t];
            int oj = jt * 32 + t;
            g_x1[oj] = fmaxf(s + __ldg(&bf1[oj]), 0.f);
        }
        gbar(1, 32);                               // publish x1
        return;
    }

    if (b <= 32) {
        // ---------------- FC2: full K=512, 32 outputs ----------------------
        const int jt = b - 17;
        {
            const float4* W4 = (const float4*)Wf2;
            float4* ws4 = (float4*)ws;
            for (int i = t; i < FC2_K * 8; i += NTHREADS) {
                int k = i >> 3, c = i & 7;
                ws4[k * 8 + c] = W4[k * (FC2_OUT / 4) + jt * 8 + c];
            }
        }
        gbar(1, 32);                               // wait for x1
        sx[t] = __ldcg(&g_x1[t]);
        __syncthreads();
        float acc = 0.f;
        #pragma unroll 8
        for (int k = kg; k < FC2_K; k += 16) acc += sx[k] * ws[k * 32 + j];
        red[t] = acc;
        __syncthreads();
        if (t < 32) {
            float s = red[t];
            #pragma unroll
            for (int g = 1; g < 16; g++) s += red[g * 32 + t];
            int oj = jt * 32 + t;
            g_x2[oj] = fmaxf(s + __ldg(&bf2[oj]), 0.f);
        }
        gbar(2, 24);                               // publish x2
        return;
    }

    // ---------------- FC3: full K=512, 32 outputs --------------------------
    {
        const int jt = b - 33;
        {
            const float4* W4 = (const float4*)Wf3;
            float4* ws4 = (float4*)ws;
            for (int i = t; i < FC3_K * 8; i += NTHREADS) {
                int k = i >> 3, c = i & 7;
                ws4[k * 8 + c] = W4[k * (FC3_OUT / 4) + jt * 8 + c];
            }
        }
        gbar(2, 24);                               // wait for x2
        sx[t] = __ldcg(&g_x2[t]);
        __syncthreads();
        float acc = 0.f;
        #pragma unroll 8
        for (int k = kg; k < FC3_K; k += 16) acc += sx[k] * ws[k * 32 + j];
        red[t] = acc;
        __syncthreads();
        if (t < 32) {
            float s = red[t];
            #pragma unroll
            for (int g = 1; g < 16; g++) s += red[g * 32 + t];
            int oj = jt * 32 + t;
            out[oj] = fmaxf(s + __ldg(&bf3[oj]), 0.f);
        }
    }
}

// ---------------------------------------------------------------------------
extern "C" void kernel_launch(void* const* d_in, const int* in_sizes, int n_in,
                              void* d_out, int out_size)
{
    const float* state = (const float*)d_in[0];
    const int*   edges = (const int*)  d_in[1];
    const int n_edges  = in_sizes[1] / 2;

    const float* W1  = (const float*)d_in[2];
    const float* b1  = (const float*)d_in[3];
    const float* W2  = (const float*)d_in[4];
    const float* b2  = (const float*)d_in[5];
    const float* Wf1 = (const float*)d_in[6];
    const float* bf1 = (const float*)d_in[7];
    const float* Wf2 = (const float*)d_in[8];
    const float* bf2 = (const float*)d_in[9];
    const float* Wf3 = (const float*)d_in[10];
    const float* bf3 = (const float*)d_in[11];
    float* out = (float*)d_out;

    static bool attr_set = false;
    if (!attr_set) {
        cudaFuncSetAttribute(fused_net_kernel,
                             cudaFuncAttributeMaxDynamicSharedMemorySize,
                             SMEM_BYTES);
        attr_set = true;
    }

    fused_net_kernel<<<NBLK, NTHREADS, SMEM_BYTES>>>(
        state, edges, n_edges, W1, b1, W2, b2,
        Wf1, bf1, Wf2, bf2, Wf3, bf3, out);
}

// round 4
// speedup vs baseline: 1.2691x; 1.2691x over previous
#include <cuda_runtime.h>
#include <math.h>

#define NN        21
#define NN2       441
#define NFEAT     128
#define FC1_OUT   512
#define FC2_OUT   512
#define FC3_OUT   256
#define FC1_K     441
#define FC2_K     512
#define FC3_K     512

#define NBLK      41           // b0 GCN | b1-16 FC1 | b17-32 FC2 | b33-40 FC3
#define NTHREADS  512

// ---- global scratch (allocation-free) ----
__device__ float g_v[448];
__device__ float g_x1[512];
__device__ float g_x2[512];

// ---- monotonic publish flags (never reset; consumers sample at entry) ----
// padded to separate cache lines
__device__ unsigned g_fv[32];          // v ready        (slot 0)
__device__ unsigned g_fx1[16 * 32];    // x1 tile w ready (slot w*32)
__device__ unsigned g_fx2[16 * 32];    // x2 tile w ready

__device__ __forceinline__ unsigned ld_acq(unsigned* p) {
    unsigned v;
    asm volatile("ld.acquire.gpu.global.u32 %0, [%1];" : "=r"(v) : "l"(p) : "memory");
    return v;
}
__device__ __forceinline__ unsigned ld_plain(unsigned* p) {
    unsigned v;
    asm volatile("ld.global.cg.u32 %0, [%1];" : "=r"(v) : "l"(p) : "memory");
    return v;
}
__device__ __forceinline__ void publish(unsigned* p) {
    // caller: producer stores done + __syncwarp/__syncthreads + __threadfence
    asm volatile("red.release.gpu.global.add.u32 [%0], 1;" :: "l"(p) : "memory");
}
__device__ __forceinline__ void wait_flag(unsigned* p, unsigned old) {
    while (ld_acq(p) == old) { }
}

// dynamic smem: FC weights [0,65536) | red [65536,67584)
#define SMEM_BYTES 67712

__global__ void __launch_bounds__(NTHREADS, 1)
fused_net_kernel(const float* __restrict__ state,
                 const int*   __restrict__ edge_index, int n_edges,
                 const float* __restrict__ W1,  const float* __restrict__ b1,
                 const float* __restrict__ W2,  const float* __restrict__ b2,
                 const float* __restrict__ Wf1, const float* __restrict__ bf1,
                 const float* __restrict__ Wf2, const float* __restrict__ bf2,
                 const float* __restrict__ Wf3, const float* __restrict__ bf3,
                 float* __restrict__ out)
{
    extern __shared__ char smem[];
    const int t = threadIdx.x;
    const int b = blockIdx.x;

    if (b == 0) {
        // ================= GCN front-end (batch element 0 only) ============
        float* sA    = (float*)smem;              // 448
        float* sBufA = sA    + 448;               // 448
        float* sBufB = sBufA + 448;               // 448
        float* sX    = sBufB + 448;               // 21*128
        float* sW1g  = sX    + NN * NFEAT;        // 128*21
        float* sW2g  = sW1g  + NFEAT * NN;        // 448
        float* sb1   = sW2g  + 448;               // 32
        float* sb2   = sb1   + 32;                // 32
        float* sdinv = sb2   + 32;                // 32

        if (t >= 448) {
            // ---- adjacency group: 64 threads, named barrier 1 ----
            const int u = t - 448;
            for (int i = u; i < NN2; i += 64) sA[i] = 0.f;
            asm volatile("bar.sync 1, 64;" ::: "memory");
            for (int e = u; e < n_edges; e += 64) {
                int r = edge_index[e];
                int c = edge_index[n_edges + e];
                atomicAdd(&sA[r * NN + c], 1.0f);
            }
            asm volatile("bar.sync 1, 64;" ::: "memory");
            if (u < NN) sA[u * NN + u] += 1.0f;
            asm volatile("bar.sync 1, 64;" ::: "memory");
            if (u < NN) {
                float d = 0.f;
                #pragma unroll
                for (int i = 0; i < NN; i++) d += sA[i * NN + u];
                sdinv[u] = (d > 0.f) ? rsqrtf(d) : 0.f;
            }
            asm volatile("bar.sync 1, 64;" ::: "memory");
            for (int i = u; i < NN2; i += 64) {
                int ii = i / NN, jj = i % NN;
                sA[i] *= sdinv[ii] * sdinv[jj];
            }
        } else {
            // ---- h1 group: 448 threads, named barrier 2 ----
            const float4* X4  = (const float4*)state;
            const float4* W14 = (const float4*)W1;
            float4* sX4  = (float4*)sX;
            float4* sW14 = (float4*)sW1g;
            for (int i = t; i < (NN * NFEAT) / 4; i += 448) sX4[i]  = X4[i];
            for (int i = t; i < (NFEAT * NN) / 4; i += 448) sW14[i] = W14[i];
            if (t < NN2) sW2g[t] = W2[t];
            if (t < NN)  sb1[t] = b1[t];
            if (t >= 32 && t < 32 + NN) sb2[t - 32] = b2[t - 32];
            asm volatile("bar.sync 2, 448;" ::: "memory");
            if (t < NN2) {                 // h1 = X @ W1
                int i = t / NN, j = t % NN;
                float acc = 0.f;
                #pragma unroll 8
                for (int f = 0; f < NFEAT; f++) acc += sX[i * NFEAT + f] * sW1g[f * NN + j];
                sBufA[t] = acc;
            }
        }
        __syncthreads();

        if (t < NN2) {                     // g1 = A @ h1 + b1
            int i = t / NN, j = t % NN;
            float acc = sb1[j];
            #pragma unroll
            for (int k = 0; k < NN; k++) acc += sA[i * NN + k] * sBufA[k * NN + j];
            sBufB[t] = acc;
        }
        __syncthreads();

        if (t < NN2) {                     // h2 = g1 @ W2
            int i = t / NN, j = t % NN;
            float acc = 0.f;
            #pragma unroll
            for (int f = 0; f < NN; f++) acc += sBufB[i * NN + f] * sW2g[f * NN + j];
            sBufA[t] = acc;
        }
        __syncthreads();

        if (t < NN2) {                     // v = A @ h2 + b2
            int i = t / NN, j = t % NN;
            float acc = sb2[j];
            #pragma unroll
            for (int k = 0; k < NN; k++) acc += sA[i * NN + k] * sBufA[k * NN + j];
            g_v[t] = acc;
        }
        __syncthreads();
        if (t == 0) { __threadfence(); publish(&g_fv[0]); }
        return;
    }

    // ======================= FC blocks =====================================
    float* ws  = (float*)smem;                    // [K x 32]
    float* red = (float*)(smem + 65536);          // [512]

    const int j    = t & 31;                      // lane = output-in-tile
    const int kg   = t >> 5;                      // warp id = k-chunk id

    if (b <= 16) {
        // ---------------- FC1: K=441, 32 outputs, warp k-chunks of 28 ------
        const int jt = b - 1;
        const unsigned old = ld_plain(&g_fv[0]);          // sample early
        const float bias = (t < 32) ? __ldg(&bf1[jt * 32 + t]) : 0.f;
        {   // preload weights (float4): 441 rows x 8 quads
            const float4* W4 = (const float4*)Wf1;
            float4* ws4 = (float4*)ws;
            for (int i = t; i < FC1_K * 8; i += NTHREADS) {
                int k = i >> 3, c = i & 7;
                ws4[k * 8 + c] = W4[k * (FC1_OUT / 4) + jt * 8 + c];
            }
        }
        const int k0   = kg * 28;
        const int klen = min(FC1_K - k0, 28);
        wait_flag(&g_fv[0], old);
        float xv = (j < klen) ? __ldcg(&g_v[k0 + j]) : 0.f;
        float acc = 0.f;
        for (int kk = 0; kk < klen; kk++)
            acc += __shfl_sync(0xffffffffu, xv, kk) * ws[(k0 + kk) * 32 + j];
        red[t] = acc;
        __syncthreads();
        if (t < 32) {
            float s = red[t];
            #pragma unroll
            for (int g = 1; g < 16; g++) s += red[g * 32 + t];
            g_x1[jt * 32 + t] = fmaxf(s + bias, 0.f);
            __syncwarp();
            if (t == 0) { __threadfence(); publish(&g_fx1[jt * 32]); }
        }
        return;
    }

    if (b <= 32) {
        // ---------------- FC2: K=512, 32 outputs, warp k-chunks of 32 ------
        const int jt = b - 17;
        unsigned old;
        if (j == 0) old = ld_plain(&g_fx1[kg * 32]);      // per-warp flag
        old = __shfl_sync(0xffffffffu, old, 0);
        const float bias = (t < 32) ? __ldg(&bf2[jt * 32 + t]) : 0.f;
        {
            const float4* W4 = (const float4*)Wf2;
            float4* ws4 = (float4*)ws;
            for (int i = t; i < FC2_K * 8; i += NTHREADS) {
                int k = i >> 3, c = i & 7;
                ws4[k * 8 + c] = W4[k * (FC2_OUT / 4) + jt * 8 + c];
            }
        }
        const int k0 = kg * 32;
        wait_flag(&g_fx1[kg * 32], old);
        float xv = __ldcg(&g_x1[k0 + j]);
        float acc = 0.f;
        #pragma unroll
        for (int kk = 0; kk < 32; kk++)
            acc += __shfl_sync(0xffffffffu, xv, kk) * ws[(k0 + kk) * 32 + j];
        red[t] = acc;
        __syncthreads();
        if (t < 32) {
            float s = red[t];
            #pragma unroll
            for (int g = 1; g < 16; g++) s += red[g * 32 + t];
            g_x2[jt * 32 + t] = fmaxf(s + bias, 0.f);
            __syncwarp();
            if (t == 0) { __threadfence(); publish(&g_fx2[jt * 32]); }
        }
        return;
    }

    // ---------------- FC3: K=512, 32 outputs, warp k-chunks of 32 ----------
    {
        const int jt = b - 33;
        unsigned old;
        if (j == 0) old = ld_plain(&g_fx2[kg * 32]);
        old = __shfl_sync(0xffffffffu, old, 0);
        const float bias = (t < 32) ? __ldg(&bf3[jt * 32 + t]) : 0.f;
        {
            const float4* W4 = (const float4*)Wf3;
            float4* ws4 = (float4*)ws;
            for (int i = t; i < FC3_K * 8; i += NTHREADS) {
                int k = i >> 3, c = i & 7;
                ws4[k * 8 + c] = W4[k * (FC3_OUT / 4) + jt * 8 + c];
            }
        }
        const int k0 = kg * 32;
        wait_flag(&g_fx2[kg * 32], old);
        float xv = __ldcg(&g_x2[k0 + j]);
        float acc = 0.f;
        #pragma unroll
        for (int kk = 0; kk < 32; kk++)
            acc += __shfl_sync(0xffffffffu, xv, kk) * ws[(k0 + kk) * 32 + j];
        red[t] = acc;
        __syncthreads();
        if (t < 32) {
            float s = red[t];
            #pragma unroll
            for (int g = 1; g < 16; g++) s += red[g * 32 + t];
            out[jt * 32 + t] = fmaxf(s + bias, 0.f);
        }
    }
}

// ---------------------------------------------------------------------------
extern "C" void kernel_launch(void* const* d_in, const int* in_sizes, int n_in,
                              void* d_out, int out_size)
{
    const float* state = (const float*)d_in[0];
    const int*   edges = (const int*)  d_in[1];
    const int n_edges  = in_sizes[1] / 2;

    const float* W1  = (const float*)d_in[2];
    const float* b1  = (const float*)d_in[3];
    const float* W2  = (const float*)d_in[4];
    const float* b2  = (const float*)d_in[5];
    const float* Wf1 = (const float*)d_in[6];
    const float* bf1 = (const float*)d_in[7];
    const float* Wf2 = (const float*)d_in[8];
    const float* bf2 = (const float*)d_in[9];
    const float* Wf3 = (const float*)d_in[10];
    const float* bf3 = (const float*)d_in[11];
    float* out = (float*)d_out;

    static bool attr_set = false;
    if (!attr_set) {
        cudaFuncSetAttribute(fused_net_kernel,
                             cudaFuncAttributeMaxDynamicSharedMemorySize,
                             SMEM_BYTES);
        attr_set = true;
    }

    fused_net_kernel<<<NBLK, NTHREADS, SMEM_BYTES>>>(
        state, edges, n_edges, W1, b1, W2, b2,
        Wf1, bf1, Wf2, bf2, Wf3, bf3, out);
}